// round 14
// baseline (speedup 1.0000x reference)
#include <cuda_runtime.h>
#include <cuda_bf16.h>
#include <cstdint>

#define BATCH  32768
#define NCODES 8192
#define DIM    256
#define BM     128
#define BN_H   128                  // codes per tile (per half)
#define NCT_H  32                   // code tiles per half (32*128 = 4096)
#define NCHUNK_H 128                // 16KB chunks per half
#define CAP    32
#define MARGIN 3e-4f
#define NTHR   512

// ---------------- device scratch ----------------
__device__ float  g_z2[BATCH];
__device__ float  g_e2[NCODES];
__device__ double g_part[BATCH];
__device__ int    g_candIdx[BATCH * CAP];
__device__ int    g_candCnt[BATCH];
// bf16 codebook, PRE-PERMUTED into mma-fragment order at 128-code granularity:
// [ct 64][kc 4][ks 4][ntpair 8][lane 32][16B]   (chunk = ct*4+kc = 16384 B)
__device__ __nv_bfloat16 g_Cb[NCODES * DIM];

// ---------------- smem layout (bytes) ----------------
#define ATILE   528                           // 512B fragment tile + 16B pad
#define SMA_SZ  (8 * 16 * ATILE)              // 67584 : 8 mtiles x 16 k16-tiles
#define BCHUNK  16384
#define SMB     SMA_SZ                        // 4 buffers: [half*2 + parity]
#define SMQB    (SMB + 4 * BCHUNK)            // 2 x qbuf[128][4] floats
#define SM_TOT  (SMQB + 2 * 128 * 4 * 4)      // 137216

__device__ __forceinline__ uint32_t smem_u32(const void* p) {
    uint32_t a;
    asm("{ .reg .u64 t; cvta.to.shared.u64 t, %1; cvt.u32.u64 %0, t; }" : "=r"(a) : "l"(p));
    return a;
}
__device__ __forceinline__ void cp16(uint32_t dst, const void* src) {
    asm volatile("cp.async.cg.shared.global [%0], [%1], 16;" :: "r"(dst), "l"(src));
}
__device__ __forceinline__ uint32_t packbf(float x, float y) {
    __nv_bfloat162 p = {__float2bfloat16(x), __float2bfloat16(y)};
    return *(uint32_t*)&p;
}
__device__ __forceinline__ void mma_bf16(float* d, const uint4& a, uint32_t b0, uint32_t b1) {
    asm volatile(
        "mma.sync.aligned.m16n8k16.row.col.f32.bf16.bf16.f32 "
        "{%0,%1,%2,%3}, {%4,%5,%6,%7}, {%8,%9}, {%0,%1,%2,%3};"
        : "+f"(d[0]), "+f"(d[1]), "+f"(d[2]), "+f"(d[3])
        : "r"(a.x), "r"(a.y), "r"(a.z), "r"(a.w), "r"(b0), "r"(b1));
}
__device__ __forceinline__ void half_bar(int half) {
    asm volatile("bar.sync %0, %1;" :: "r"(1 + half), "r"(256) : "memory");
}

// ---------------- codebook fp32 -> bf16, permuted (128-code tiles) ----------
__global__ void cvtC_kernel(const float* __restrict__ x) {
    int i = blockIdx.x * blockDim.x + threadIdx.x;   // one float4 = 4 dims of 1 code
    int n = i >> 6, c4 = i & 63;
    float4 v = ((const float4*)x)[i];
    uint32_t p0 = packbf(v.x, v.y);                  // dims d, d+1
    uint32_t p1 = packbf(v.z, v.w);                  // dims d+2, d+3
    int d = c4 * 4;
    int ct = n >> 7, nc = n & 127;
    int g = nc & 7, nt = nc >> 3;                    // nt 0..15
    int ntpair = nt >> 1, ntodd = nt & 1;            // ntpair 0..7
    int kc = d >> 6, ks = (d >> 4) & 3, k16 = d & 15;
    int w = ntodd * 2 + (k16 >> 3);                  // word slot
    char* base = (char*)g_Cb + ((size_t)ct * 4 + kc) * BCHUNK
               + ((ks * 8 + ntpair) * 32) * 16 + w * 4;
    int tq0 = (k16 & 7) >> 1;
    int tq1 = ((k16 + 2) & 7) >> 1;
    *(uint32_t*)(base + (g * 4 + tq0) * 16) = p0;
    *(uint32_t*)(base + (g * 4 + tq1) * 16) = p1;
}

// ---------------- row sum-of-squares (bit-matches reference grid) ----------
__global__ void rowsq_z_kernel(const float* __restrict__ x) {
    int warp = (blockIdx.x * blockDim.x + threadIdx.x) >> 5;
    int lane = threadIdx.x & 31;
    if (warp >= BATCH) return;
    const float* r = x + (size_t)warp * DIM;
    float acc = 0.f;
#pragma unroll
    for (int j = 0; j < DIM; j += 32) { float v = r[j + lane]; acc = fmaf(v, v, acc); }
#pragma unroll
    for (int off = 16; off; off >>= 1) acc += __shfl_down_sync(0xffffffffu, acc, off);
    if (lane == 0) { g_z2[warp] = acc; g_candCnt[warp] = 0; }
}
__global__ void rowsq_e_kernel(const float* __restrict__ x) {
    int warp = (blockIdx.x * blockDim.x + threadIdx.x) >> 5;
    int lane = threadIdx.x & 31;
    if (warp >= NCODES) return;
    const float* r = x + (size_t)warp * DIM;
    float acc = 0.f;
#pragma unroll
    for (int j = 0; j < DIM; j += 32) { float v = r[j + lane]; acc = fmaf(v, v, acc); }
#pragma unroll
    for (int off = 16; off; off >>= 1) acc += __shfl_down_sync(0xffffffffu, acc, off);
    if (lane == 0) g_e2[warp] = acc;
}

// ---------------- per-half B chunk issue (256 threads of the half) ----------
__device__ __forceinline__ void issueB(uint32_t sb, int half, int chunk, int htid) {
    uint32_t bbuf = sb + SMB + (uint32_t)(half * 2 + (chunk & 1)) * BCHUNK;
    const char* src = (const char*)g_Cb + ((size_t)half * NCHUNK_H + chunk) * BCHUNK;
#pragma unroll
    for (int t = 0; t < 4; t++) {
        int q = htid + t * 256;              // 1024 x 16B
        cp16(bbuf + q * 16, src + (size_t)q * 16);
    }
    asm volatile("cp.async.commit_group;" ::: "memory");
}

// ---------------- bf16 mma distance kernel, two independent halves ----------
__global__ __launch_bounds__(NTHR, 1)
void dist_mma_kernel(const float* __restrict__ Z) {
    extern __shared__ char sm[];
    const uint32_t sb = smem_u32(sm);
    const int tid  = threadIdx.x;
    const int wid  = tid >> 5;
    const int lane = tid & 31;
    const int g    = lane >> 2;
    const int tq   = lane & 3;
    const int half = wid >> 3;           // 0..1 : code-range half
    const int wr   = (wid >> 2) & 1;     // 0..1 : 64-row slab (4 mtiles each)
    const int wc   = wid & 3;            // 0..3 : 32-code slab (4 ntiles)
    const int htid = tid & 255;
    const int rowBase = blockIdx.x * BM;
    float* qbuf = (float*)(sm + SMQB) + half * 512;   // [128][4] per half

    issueB(sb, half, 0, htid);           // each half's B0 overlaps A staging

    // ---- stage A (128 x 256) fp32 -> bf16 pairs, fragment-permuted (proven) ----
#pragma unroll
    for (int l = 0; l < 16; l++) {
        int i4 = tid + l * NTHR;         // 8192 float4
        int r  = i4 >> 6;
        int c4 = i4 & 63;
        float4 v = *(const float4*)(Z + (size_t)(rowBase + r) * DIM + c4 * 4);
        uint32_t p0 = packbf(v.x, v.y);
        uint32_t p1 = packbf(v.z, v.w);
        int r16 = r & 15, mtG = r >> 4;
        int rowPart = ((r16 & 7) * 4) * 16 + ((r16 >> 3) & 1) * 4;
#pragma unroll
        for (int pi = 0; pi < 2; pi++) {
            int c = 2 * c4 + pi;
            int kt = c >> 3, c8 = c & 7;
            int off = (mtG * 16 + kt) * ATILE + rowPart + (c8 & 3) * 16 + ((c8 >> 2) * 2) * 4;
            *(uint32_t*)(sm + off) = pi ? p1 : p0;
        }
    }
    __syncthreads();                     // A visible to all; halves now independent

    float wmRun[4][2];
#pragma unroll
    for (int a = 0; a < 4; a++) { wmRun[a][0] = wmRun[a][1] = __int_as_float(0x7f800000); }

    for (int ct = 0; ct < NCT_H; ct++) {
        float acc[4][4][4];
#pragma unroll
        for (int a = 0; a < 4; a++)
#pragma unroll
            for (int b = 0; b < 4; b++)
#pragma unroll
                for (int e = 0; e < 4; e++) acc[a][b][e] = 0.f;

        for (int kc = 0; kc < 4; kc++) {
            const int chunk = ct * 4 + kc;
            asm volatile("cp.async.wait_group 0;" ::: "memory");
            half_bar(half);
            if (chunk + 1 < NCHUNK_H) issueB(sb, half, chunk + 1, htid);

            const uint32_t bo = SMB + (uint32_t)(half * 2 + (chunk & 1)) * BCHUNK;
#pragma unroll
            for (int ks = 0; ks < 4; ks++) {          // four k16 steps per chunk
                uint4 afr[4];
#pragma unroll
                for (int mt = 0; mt < 4; mt++)
                    afr[mt] = *(const uint4*)(sm + ((wr * 4 + mt) * 16 + kc * 4 + ks) * ATILE + lane * 16);
#pragma unroll
                for (int pp = 0; pp < 2; pp++) {      // ntpairs wc*2, wc*2+1
                    uint4 bfr = *(const uint4*)(sm + bo + (((ks * 8 + wc * 2 + pp) * 32) + lane) * 16);
#pragma unroll
                    for (int mt = 0; mt < 4; mt++) {
                        mma_bf16(acc[mt][pp * 2],     afr[mt], bfr.x, bfr.y);
                        mma_bf16(acc[mt][pp * 2 + 1], afr[mt], bfr.z, bfr.w);
                    }
                }
            }
        }

        // ---- epilogue: dist = e2 - 2*ze, half-local rowmin, candidate append ----
        const int ctbase = half * 4096 + ct * BN_H;
        float e2v[4][2];
#pragma unroll
        for (int nt = 0; nt < 4; nt++) {
            int c = ctbase + wc * 32 + nt * 8 + 2 * tq;
            e2v[nt][0] = __ldg(&g_e2[c]);
            e2v[nt][1] = __ldg(&g_e2[c + 1]);
        }
#pragma unroll
        for (int mt = 0; mt < 4; mt++)
#pragma unroll
            for (int h = 0; h < 2; h++) {
                float m = __int_as_float(0x7f800000);
#pragma unroll
                for (int nt = 0; nt < 4; nt++)
#pragma unroll
                    for (int c01 = 0; c01 < 2; c01++) {
                        int ai = h * 2 + c01;
                        float d = fmaf(-2.f, acc[mt][nt][ai], e2v[nt][c01]);
                        acc[mt][nt][ai] = d;
                        m = fminf(m, d);
                    }
                m = fminf(m, __shfl_xor_sync(0xffffffffu, m, 1));
                m = fminf(m, __shfl_xor_sync(0xffffffffu, m, 2));
                wmRun[mt][h] = fminf(wmRun[mt][h], m);
                if (tq == 0)
                    qbuf[(wr * 64 + mt * 16 + g + h * 8) * 4 + wc] = wmRun[mt][h];
            }
        half_bar(half);
#pragma unroll
        for (int mt = 0; mt < 4; mt++)
#pragma unroll
            for (int h = 0; h < 2; h++) {
                int r = wr * 64 + mt * 16 + g + h * 8;     // covers 0..127
                float th = fminf(fminf(qbuf[r * 4 + 0], qbuf[r * 4 + 1]),
                                 fminf(qbuf[r * 4 + 2], qbuf[r * 4 + 3])) + MARGIN;
                int grow = rowBase + r;
#pragma unroll
                for (int nt = 0; nt < 4; nt++)
#pragma unroll
                    for (int c01 = 0; c01 < 2; c01++) {
                        float d = acc[mt][nt][h * 2 + c01];
                        if (d < th) {
                            int code = ctbase + wc * 32 + nt * 8 + 2 * tq + c01;
                            int pos = atomicAdd(&g_candCnt[grow], 1);
                            if (pos < CAP) g_candIdx[grow * CAP + pos] = code;
                        }
                    }
            }
        // next ct's qbuf writes are separated by its first-chunk half_bar
    }
}

// ---------------- exact refine + fused gather/output/loss -------------------
__device__ __forceinline__ float exact_dist(const float4* __restrict__ zr, int code,
                                            const float* __restrict__ C, float z2) {
    const float4* cr = (const float4*)(C + (size_t)code * DIM);
    float acc = 0.f;
#pragma unroll 4
    for (int d4 = 0; d4 < 64; d4++) {
        float4 a = zr[d4], b = cr[d4];
        acc = fmaf(a.x, b.x, acc); acc = fmaf(a.y, b.y, acc);
        acc = fmaf(a.z, b.z, acc); acc = fmaf(a.w, b.w, acc);
    }
    float t = z2 + g_e2[code];
    return fmaf(-2.f, acc, t);
}

__global__ __launch_bounds__(256, 6)
void refine_gather_kernel(const float* __restrict__ Z, const float* __restrict__ C,
                          float* __restrict__ outZ, float* __restrict__ outIdx) {
    int gt = blockIdx.x * blockDim.x + threadIdx.x;
    int row = gt >> 3, slot = gt & 7;
    if (row >= BATCH) return;
    int cnt = g_candCnt[row];
    const float4* zr = (const float4*)(Z + (size_t)row * DIM);
    float z2 = g_z2[row];
    float bd = __int_as_float(0x7f800000);
    int bi = 0x7fffffff;
    if (cnt > 0 && cnt <= CAP) {
        for (int s = slot; s < cnt; s += 8) {
            int code = g_candIdx[row * CAP + s];
            float dist = exact_dist(zr, code, C, z2);
            if (dist < bd || (dist == bd && code < bi)) { bd = dist; bi = code; }
        }
    } else {  // overflow OR empty (defensive): exact full scan
        for (int code = slot; code < NCODES; code += 8) {
            float dist = exact_dist(zr, code, C, z2);
            if (dist < bd || (dist == bd && code < bi)) { bd = dist; bi = code; }
        }
    }
#pragma unroll
    for (int off = 4; off; off >>= 1) {          // xor butterfly: all 8 lanes get result
        float od = __shfl_xor_sync(0xffffffffu, bd, off);
        int oi = __shfl_xor_sync(0xffffffffu, bi, off);
        if (od < bd || (od == bd && oi < bi)) { bd = od; bi = oi; }
    }
    const float4* er = (const float4*)(C + (size_t)bi * DIM);
    float4* orow = (float4*)(outZ + (size_t)row * DIM);
    double s = 0.0;
#pragma unroll
    for (int j = 0; j < 8; j++) {
        int i = slot * 8 + j;
        float4 z = zr[i], e = er[i];
        float dx = e.x - z.x, dy = e.y - z.y, dz = e.z - z.z, dw = e.w - z.w;
        float4 o;
        o.x = z.x + dx; o.y = z.y + dy; o.z = z.z + dz; o.w = z.w + dw;
        orow[i] = o;
        s += (double)(dx * dx) + (double)(dy * dy) + (double)(dz * dz) + (double)(dw * dw);
    }
#pragma unroll
    for (int off = 4; off; off >>= 1) s += __shfl_xor_sync(0xffffffffu, s, off);
    if (slot == 0) { g_part[row] = s; outIdx[row] = (float)bi; }
}

__global__ void finalize_kernel(float* __restrict__ outS) {
    __shared__ double red[256];
    int t = threadIdx.x;
    double s = 0.0;
    for (int i = t; i < BATCH; i += 256) s += g_part[i];
    red[t] = s;
    __syncthreads();
#pragma unroll
    for (int off = 128; off; off >>= 1) {
        if (t < off) red[t] += red[t + off];
        __syncthreads();
    }
    if (t == 0) {
        float cb = (float)(red[0] / (double)((size_t)BATCH * DIM));
        float commit = cb;
        float vq = cb + 0.25f * commit;
        outS[0] = vq; outS[1] = cb; outS[2] = commit;
    }
}

// ---------------------------------------------------------------------------
extern "C" void kernel_launch(void* const* d_in, const int* in_sizes, int n_in,
                              void* d_out, int out_size) {
    (void)in_sizes; (void)n_in; (void)out_size;
    const float* Z = (const float*)d_in[0];
    const float* C = (const float*)d_in[1];
    float* out    = (float*)d_out;
    float* outZ   = out;
    float* outIdx = out + (size_t)BATCH * DIM;
    float* outS   = outIdx + BATCH;

    static bool attrSet = false;
    if (!attrSet) {
        cudaFuncSetAttribute(dist_mma_kernel,
                             cudaFuncAttributeMaxDynamicSharedMemorySize, SM_TOT);
        attrSet = true;
    }

    cvtC_kernel<<<(NCODES * DIM / 4) / 256, 256>>>(C);
    rowsq_z_kernel<<<(BATCH * 32) / 256, 256>>>(Z);
    rowsq_e_kernel<<<(NCODES * 32) / 256, 256>>>(C);
    dist_mma_kernel<<<BATCH / BM, NTHR, SM_TOT>>>(Z);
    refine_gather_kernel<<<(BATCH * 8) / 256, 256>>>(Z, C, outZ, outIdx);
    finalize_kernel<<<1, 256>>>(outS);
}

// round 15
// speedup vs baseline: 7.3385x; 7.3385x over previous
#include <cuda_runtime.h>
#include <cuda_bf16.h>
#include <cstdint>

#define BATCH  32768
#define NCODES 8192
#define DIM    256
#define BM     64
#define BN     256
#define NCT    (NCODES / BN)        // 32 code tiles
#define DC     64                   // dims per cp.async chunk
#define NKC    (DIM / DC)           // 4 chunks per code tile
#define NCHUNK (NCT * NKC)          // 128
#define CAP    32
#define MARGIN 3e-4f
#define NTHR   256

// ---------------- device scratch ----------------
__device__ float  g_z2[BATCH];
__device__ float  g_e2[NCODES];
__device__ double g_part[BATCH];
__device__ int    g_candIdx[BATCH * CAP];
__device__ int    g_candCnt[BATCH];
// bf16 codebook, PRE-PERMUTED into mma-fragment order (R12-proven layout):
// [ct 32][kc 4][ks 4][ntpair 16][lane 32][16B]  (chunk = 32768 B)
__device__ __nv_bfloat16 g_Cb[NCODES * DIM];

// ---------------- smem layout (bytes) ----------------
#define ATILE   528                           // 512B fragment tile + 16B pad
#define SMA_SZ  (4 * 16 * ATILE)              // 33792 : 4 mtiles x 16 k16-tiles
#define BCHUNK  32768                         // contiguous permuted chunk
#define SMB0    SMA_SZ
#define SMB1    (SMB0 + BCHUNK)
#define SMQB    (SMB1 + BCHUNK)               // qbuf[64][4] floats
#define SM_TOT  (SMQB + 64 * 4 * 4)           // 100352  (x2 CTAs = 200704)

__device__ __forceinline__ uint32_t smem_u32(const void* p) {
    uint32_t a;
    asm("{ .reg .u64 t; cvta.to.shared.u64 t, %1; cvt.u32.u64 %0, t; }" : "=r"(a) : "l"(p));
    return a;
}
__device__ __forceinline__ void cp16(uint32_t dst, const void* src) {
    asm volatile("cp.async.cg.shared.global [%0], [%1], 16;" :: "r"(dst), "l"(src));
}
__device__ __forceinline__ uint32_t packbf(float x, float y) {
    __nv_bfloat162 p = {__float2bfloat16(x), __float2bfloat16(y)};
    return *(uint32_t*)&p;
}
__device__ __forceinline__ void mma_bf16(float* d, const uint4& a, uint32_t b0, uint32_t b1) {
    asm volatile(
        "mma.sync.aligned.m16n8k16.row.col.f32.bf16.bf16.f32 "
        "{%0,%1,%2,%3}, {%4,%5,%6,%7}, {%8,%9}, {%0,%1,%2,%3};"
        : "+f"(d[0]), "+f"(d[1]), "+f"(d[2]), "+f"(d[3])
        : "r"(a.x), "r"(a.y), "r"(a.z), "r"(a.w), "r"(b0), "r"(b1));
}

// ---------------- codebook fp32 -> bf16, permuted (R12 verbatim) ------------
__global__ void cvtC_kernel(const float* __restrict__ x) {
    int i = blockIdx.x * blockDim.x + threadIdx.x;   // one float4 = 4 dims of 1 code
    int n = i >> 6, c4 = i & 63;
    float4 v = ((const float4*)x)[i];
    uint32_t p0 = packbf(v.x, v.y);
    uint32_t p1 = packbf(v.z, v.w);
    int d = c4 * 4;
    int ct = n >> 8, nc = n & 255;
    int g = nc & 7, nt = nc >> 3;
    int ntpair = nt >> 1, ntodd = nt & 1;
    int kc = d >> 6, ks = (d >> 4) & 3, k16 = d & 15;
    int w = ntodd * 2 + (k16 >> 3);
    char* base = (char*)g_Cb + (size_t)ct * 131072 + kc * 32768
               + ((ks * 16 + ntpair) * 32) * 16 + w * 4;
    int tq0 = (k16 & 7) >> 1;
    int tq1 = ((k16 + 2) & 7) >> 1;
    *(uint32_t*)(base + (g * 4 + tq0) * 16) = p0;
    *(uint32_t*)(base + (g * 4 + tq1) * 16) = p1;
}

// ---------------- row sum-of-squares (bit-matches reference grid) ----------
__global__ void rowsq_z_kernel(const float* __restrict__ x) {
    int warp = (blockIdx.x * blockDim.x + threadIdx.x) >> 5;
    int lane = threadIdx.x & 31;
    if (warp >= BATCH) return;
    const float* r = x + (size_t)warp * DIM;
    float acc = 0.f;
#pragma unroll
    for (int j = 0; j < DIM; j += 32) { float v = r[j + lane]; acc = fmaf(v, v, acc); }
#pragma unroll
    for (int off = 16; off; off >>= 1) acc += __shfl_down_sync(0xffffffffu, acc, off);
    if (lane == 0) { g_z2[warp] = acc; g_candCnt[warp] = 0; }
}
__global__ void rowsq_e_kernel(const float* __restrict__ x) {
    int warp = (blockIdx.x * blockDim.x + threadIdx.x) >> 5;
    int lane = threadIdx.x & 31;
    if (warp >= NCODES) return;
    const float* r = x + (size_t)warp * DIM;
    float acc = 0.f;
#pragma unroll
    for (int j = 0; j < DIM; j += 32) { float v = r[j + lane]; acc = fmaf(v, v, acc); }
#pragma unroll
    for (int off = 16; off; off >>= 1) acc += __shfl_down_sync(0xffffffffu, acc, off);
    if (lane == 0) g_e2[warp] = acc;
}

// ---------------- B chunk issue: contiguous 32 KB permuted chunk ------------
__device__ __forceinline__ void issueB(uint32_t sb, int chunk, int tid) {
    uint32_t bbuf = sb + ((chunk & 1) ? SMB1 : SMB0);
    const char* src = (const char*)g_Cb + (size_t)chunk * 32768;
#pragma unroll
    for (int t = 0; t < 8; t++) {
        int q = tid + t * NTHR;              // 2048 x 16B
        cp16(bbuf + q * 16, src + (size_t)q * 16);
    }
    asm volatile("cp.async.commit_group;" ::: "memory");
}

// ---------------- bf16 mma distance kernel + candidate capture --------------
__global__ __launch_bounds__(NTHR, 2)
void dist_mma_kernel(const float* __restrict__ Z) {
    extern __shared__ char sm[];
    const uint32_t sb = smem_u32(sm);
    const int tid  = threadIdx.x;
    const int wid  = tid >> 5;
    const int lane = tid & 31;
    const int g    = lane >> 2;
    const int tq   = lane & 3;
    const int wr   = wid >> 2;           // 0..1 : 32-row slab
    const int wc   = wid & 3;            // 0..3 : 64-code slab
    const int rowBase = blockIdx.x * BM;
    float* qbuf = (float*)(sm + SMQB);   // [64][4]

    issueB(sb, 0, tid);                  // async B0 overlaps A staging

    // ---- stage A (64 x 256) fp32 -> bf16 pairs, fragment-permuted (R12) ----
#pragma unroll
    for (int l = 0; l < 16; l++) {
        int i4 = tid + l * NTHR;         // 4096 float4
        int r  = i4 >> 6;
        int c4 = i4 & 63;
        float4 v = *(const float4*)(Z + (size_t)(rowBase + r) * DIM + c4 * 4);
        uint32_t p0 = packbf(v.x, v.y);
        uint32_t p1 = packbf(v.z, v.w);
        int r16 = r & 15, mtG = r >> 4;  // mtG 0..3
        int rowPart = ((r16 & 7) * 4) * 16 + ((r16 >> 3) & 1) * 4;
#pragma unroll
        for (int pi = 0; pi < 2; pi++) {
            int c = 2 * c4 + pi;
            int kt = c >> 3, c8 = c & 7;
            int off = (mtG * 16 + kt) * ATILE + rowPart + (c8 & 3) * 16 + ((c8 >> 2) * 2) * 4;
            *(uint32_t*)(sm + off) = pi ? p1 : p0;
        }
    }

    float wmRun[2][2];
    wmRun[0][0] = wmRun[0][1] = wmRun[1][0] = wmRun[1][1] = __int_as_float(0x7f800000);

    for (int ct = 0; ct < NCT; ct++) {
        float acc[2][8][4];
#pragma unroll
        for (int a = 0; a < 2; a++)
#pragma unroll
            for (int b = 0; b < 8; b++)
#pragma unroll
                for (int e = 0; e < 4; e++) acc[a][b][e] = 0.f;

        for (int kc = 0; kc < NKC; kc++) {
            const int chunk = ct * NKC + kc;
            asm volatile("cp.async.wait_group 0;" ::: "memory");
            __syncthreads();
            if (chunk + 1 < NCHUNK) issueB(sb, chunk + 1, tid);

            const uint32_t bo = (uint32_t)((chunk & 1) ? SMB1 : SMB0);
#pragma unroll
            for (int ks = 0; ks < 4; ks++) {          // four k16 steps per chunk
                uint4 afr[2];
#pragma unroll
                for (int mt = 0; mt < 2; mt++)
                    afr[mt] = *(const uint4*)(sm + ((wr * 2 + mt) * 16 + kc * 4 + ks) * ATILE + lane * 16);
#pragma unroll
                for (int pp = 0; pp < 4; pp++) {      // 4 ntpairs = 8 nt per warp
                    uint4 bfr = *(const uint4*)(sm + bo + (((ks * 16 + wc * 4 + pp) * 32) + lane) * 16);
#pragma unroll
                    for (int mt = 0; mt < 2; mt++) {
                        mma_bf16(acc[mt][pp * 2],     afr[mt], bfr.x, bfr.y);
                        mma_bf16(acc[mt][pp * 2 + 1], afr[mt], bfr.z, bfr.w);
                    }
                }
            }
        }

        // ---- epilogue: dist = e2 - 2*ze, running rowmin, candidate append ----
        const int ctbase = ct * BN;
        float e2v[8][2];
#pragma unroll
        for (int nt = 0; nt < 8; nt++) {
            int c = ctbase + wc * 64 + nt * 8 + 2 * tq;
            e2v[nt][0] = __ldg(&g_e2[c]);
            e2v[nt][1] = __ldg(&g_e2[c + 1]);
        }
#pragma unroll
        for (int mt = 0; mt < 2; mt++)
#pragma unroll
            for (int h = 0; h < 2; h++) {
                float m = __int_as_float(0x7f800000);
#pragma unroll
                for (int nt = 0; nt < 8; nt++)
#pragma unroll
                    for (int c01 = 0; c01 < 2; c01++) {
                        int ai = h * 2 + c01;
                        float d = fmaf(-2.f, acc[mt][nt][ai], e2v[nt][c01]);
                        acc[mt][nt][ai] = d;
                        m = fminf(m, d);
                    }
                m = fminf(m, __shfl_xor_sync(0xffffffffu, m, 1));
                m = fminf(m, __shfl_xor_sync(0xffffffffu, m, 2));
                wmRun[mt][h] = fminf(wmRun[mt][h], m);
                if (tq == 0)
                    qbuf[(wr * 32 + mt * 16 + g + h * 8) * 4 + wc] = wmRun[mt][h];
            }
        __syncthreads();
#pragma unroll
        for (int mt = 0; mt < 2; mt++)
#pragma unroll
            for (int h = 0; h < 2; h++) {
                int r = wr * 32 + mt * 16 + g + h * 8;   // covers 0..63
                float th = fminf(fminf(qbuf[r * 4 + 0], qbuf[r * 4 + 1]),
                                 fminf(qbuf[r * 4 + 2], qbuf[r * 4 + 3])) + MARGIN;
                int grow = rowBase + r;
#pragma unroll
                for (int nt = 0; nt < 8; nt++)
#pragma unroll
                    for (int c01 = 0; c01 < 2; c01++) {
                        float d = acc[mt][nt][h * 2 + c01];
                        if (d < th) {
                            int code = ctbase + wc * 64 + nt * 8 + 2 * tq + c01;
                            int pos = atomicAdd(&g_candCnt[grow], 1);
                            if (pos < CAP) g_candIdx[grow * CAP + pos] = code;
                        }
                    }
            }
        // next ct's qbuf writes are separated by its first-chunk barrier
    }
}

// ---------------- exact refine + fused gather/output/loss -------------------
__device__ __forceinline__ float exact_dist(const float4* __restrict__ zr, int code,
                                            const float* __restrict__ C, float z2) {
    const float4* cr = (const float4*)(C + (size_t)code * DIM);
    float acc = 0.f;
#pragma unroll 4
    for (int d4 = 0; d4 < 64; d4++) {
        float4 a = zr[d4], b = cr[d4];
        acc = fmaf(a.x, b.x, acc); acc = fmaf(a.y, b.y, acc);
        acc = fmaf(a.z, b.z, acc); acc = fmaf(a.w, b.w, acc);
    }
    float t = z2 + g_e2[code];
    return fmaf(-2.f, acc, t);
}

__global__ __launch_bounds__(256, 6)
void refine_gather_kernel(const float* __restrict__ Z, const float* __restrict__ C,
                          float* __restrict__ outZ, float* __restrict__ outIdx) {
    int gt = blockIdx.x * blockDim.x + threadIdx.x;
    int row = gt >> 3, slot = gt & 7;
    if (row >= BATCH) return;
    int cnt = g_candCnt[row];
    const float4* zr = (const float4*)(Z + (size_t)row * DIM);
    float z2 = g_z2[row];
    float bd = __int_as_float(0x7f800000);
    int bi = 0x7fffffff;
    if (cnt > 0 && cnt <= CAP) {
        for (int s = slot; s < cnt; s += 8) {
            int code = g_candIdx[row * CAP + s];
            float dist = exact_dist(zr, code, C, z2);
            if (dist < bd || (dist == bd && code < bi)) { bd = dist; bi = code; }
        }
    } else {  // overflow OR empty (defensive): exact full scan
        for (int code = slot; code < NCODES; code += 8) {
            float dist = exact_dist(zr, code, C, z2);
            if (dist < bd || (dist == bd && code < bi)) { bd = dist; bi = code; }
        }
    }
#pragma unroll
    for (int off = 4; off; off >>= 1) {          // xor butterfly: all 8 lanes get result
        float od = __shfl_xor_sync(0xffffffffu, bd, off);
        int oi = __shfl_xor_sync(0xffffffffu, bi, off);
        if (od < bd || (od == bd && oi < bi)) { bd = od; bi = oi; }
    }
    const float4* er = (const float4*)(C + (size_t)bi * DIM);
    float4* orow = (float4*)(outZ + (size_t)row * DIM);
    double s = 0.0;
#pragma unroll
    for (int j = 0; j < 8; j++) {
        int i = slot * 8 + j;
        float4 z = zr[i], e = er[i];
        float dx = e.x - z.x, dy = e.y - z.y, dz = e.z - z.z, dw = e.w - z.w;
        float4 o;
        o.x = z.x + dx; o.y = z.y + dy; o.z = z.z + dz; o.w = z.w + dw;
        orow[i] = o;
        s += (double)(dx * dx) + (double)(dy * dy) + (double)(dz * dz) + (double)(dw * dw);
    }
#pragma unroll
    for (int off = 4; off; off >>= 1) s += __shfl_xor_sync(0xffffffffu, s, off);
    if (slot == 0) { g_part[row] = s; outIdx[row] = (float)bi; }
}

__global__ void finalize_kernel(float* __restrict__ outS) {
    __shared__ double red[256];
    int t = threadIdx.x;
    double s = 0.0;
    for (int i = t; i < BATCH; i += 256) s += g_part[i];
    red[t] = s;
    __syncthreads();
#pragma unroll
    for (int off = 128; off; off >>= 1) {
        if (t < off) red[t] += red[t + off];
        __syncthreads();
    }
    if (t == 0) {
        float cb = (float)(red[0] / (double)((size_t)BATCH * DIM));
        float commit = cb;
        float vq = cb + 0.25f * commit;
        outS[0] = vq; outS[1] = cb; outS[2] = commit;
    }
}

// ---------------------------------------------------------------------------
extern "C" void kernel_launch(void* const* d_in, const int* in_sizes, int n_in,
                              void* d_out, int out_size) {
    (void)in_sizes; (void)n_in; (void)out_size;
    const float* Z = (const float*)d_in[0];
    const float* C = (const float*)d_in[1];
    float* out    = (float*)d_out;
    float* outZ   = out;
    float* outIdx = out + (size_t)BATCH * DIM;
    float* outS   = outIdx + BATCH;

    static bool attrSet = false;
    if (!attrSet) {
        cudaFuncSetAttribute(dist_mma_kernel,
                             cudaFuncAttributeMaxDynamicSharedMemorySize, SM_TOT);
        attrSet = true;
    }

    cvtC_kernel<<<(NCODES * DIM / 4) / 256, 256>>>(C);
    rowsq_z_kernel<<<(BATCH * 32) / 256, 256>>>(Z);
    rowsq_e_kernel<<<(NCODES * 32) / 256, 256>>>(C);
    dist_mma_kernel<<<BATCH / BM, NTHR, SM_TOT>>>(Z);
    refine_gather_kernel<<<(BATCH * 8) / 256, 256>>>(Z, C, outZ, outIdx);
    finalize_kernel<<<1, 256>>>(outS);
}

// round 16
// speedup vs baseline: 7.4957x; 1.0214x over previous
#include <cuda_runtime.h>
#include <cuda_bf16.h>
#include <cstdint>

#define BATCH  32768
#define NCODES 8192
#define DIM    256
#define BM     64
#define BN     256
#define NCT    (NCODES / BN)        // 32 code tiles
#define DC     64                   // dims per cp.async chunk
#define NKC    (DIM / DC)           // 4 chunks per code tile
#define NCHUNK (NCT * NKC)          // 128
#define CAP    32
#define MARGIN 3e-4f
#define NTHR   256

// ---------------- device scratch ----------------
__device__ float  g_z2[BATCH];
__device__ float  g_e2[NCODES];
__device__ double g_part[BATCH];
__device__ int    g_candIdx[BATCH * CAP];
__device__ int    g_candCnt[BATCH];
// bf16 codebook, PRE-PERMUTED into mma-fragment order (proven layout):
// [ct 32][kc 4][ks 4][ntpair 16][lane 32][16B]  (chunk = 32768 B)
__device__ __nv_bfloat16 g_Cb[NCODES * DIM];

// ---------------- smem layout (bytes) ----------------
#define ATILE   528                           // 512B fragment tile + 16B pad
#define SMA_SZ  (4 * 16 * ATILE)              // 33792 : 4 mtiles x 16 k16-tiles
#define BCHUNK  32768                         // contiguous permuted chunk
#define SMB0    SMA_SZ
#define SMB1    (SMB0 + BCHUNK)
#define SMQB    (SMB1 + BCHUNK)               // qbuf[64][4] floats
#define SM_TOT  (SMQB + 64 * 4 * 4)           // 100352  (x2 CTAs = 200704)

__device__ __forceinline__ uint32_t smem_u32(const void* p) {
    uint32_t a;
    asm("{ .reg .u64 t; cvta.to.shared.u64 t, %1; cvt.u32.u64 %0, t; }" : "=r"(a) : "l"(p));
    return a;
}
__device__ __forceinline__ void cp16(uint32_t dst, const void* src) {
    asm volatile("cp.async.cg.shared.global [%0], [%1], 16;" :: "r"(dst), "l"(src));
}
__device__ __forceinline__ uint32_t packbf(float x, float y) {
    __nv_bfloat162 p = {__float2bfloat16(x), __float2bfloat16(y)};
    return *(uint32_t*)&p;
}
__device__ __forceinline__ void mma_bf16(float* d, const uint4& a, uint32_t b0, uint32_t b1) {
    asm volatile(
        "mma.sync.aligned.m16n8k16.row.col.f32.bf16.bf16.f32 "
        "{%0,%1,%2,%3}, {%4,%5,%6,%7}, {%8,%9}, {%0,%1,%2,%3};"
        : "+f"(d[0]), "+f"(d[1]), "+f"(d[2]), "+f"(d[3])
        : "r"(a.x), "r"(a.y), "r"(a.z), "r"(a.w), "r"(b0), "r"(b1));
}

// ---------------- codebook fp32 -> bf16, permuted (proven, verbatim) --------
__global__ void cvtC_kernel(const float* __restrict__ x) {
    int i = blockIdx.x * blockDim.x + threadIdx.x;   // one float4 = 4 dims of 1 code
    int n = i >> 6, c4 = i & 63;
    float4 v = ((const float4*)x)[i];
    uint32_t p0 = packbf(v.x, v.y);
    uint32_t p1 = packbf(v.z, v.w);
    int d = c4 * 4;
    int ct = n >> 8, nc = n & 255;
    int g = nc & 7, nt = nc >> 3;
    int ntpair = nt >> 1, ntodd = nt & 1;
    int kc = d >> 6, ks = (d >> 4) & 3, k16 = d & 15;
    int w = ntodd * 2 + (k16 >> 3);
    char* base = (char*)g_Cb + (size_t)ct * 131072 + kc * 32768
               + ((ks * 16 + ntpair) * 32) * 16 + w * 4;
    int tq0 = (k16 & 7) >> 1;
    int tq1 = ((k16 + 2) & 7) >> 1;
    *(uint32_t*)(base + (g * 4 + tq0) * 16) = p0;
    *(uint32_t*)(base + (g * 4 + tq1) * 16) = p1;
}

// ---------------- row sum-of-squares (bit-matches reference grid) ----------
__global__ void rowsq_z_kernel(const float* __restrict__ x) {
    int warp = (blockIdx.x * blockDim.x + threadIdx.x) >> 5;
    int lane = threadIdx.x & 31;
    if (warp >= BATCH) return;
    const float* r = x + (size_t)warp * DIM;
    float acc = 0.f;
#pragma unroll
    for (int j = 0; j < DIM; j += 32) { float v = r[j + lane]; acc = fmaf(v, v, acc); }
#pragma unroll
    for (int off = 16; off; off >>= 1) acc += __shfl_down_sync(0xffffffffu, acc, off);
    if (lane == 0) { g_z2[warp] = acc; g_candCnt[warp] = 0; }
}
__global__ void rowsq_e_kernel(const float* __restrict__ x) {
    int warp = (blockIdx.x * blockDim.x + threadIdx.x) >> 5;
    int lane = threadIdx.x & 31;
    if (warp >= NCODES) return;
    const float* r = x + (size_t)warp * DIM;
    float acc = 0.f;
#pragma unroll
    for (int j = 0; j < DIM; j += 32) { float v = r[j + lane]; acc = fmaf(v, v, acc); }
#pragma unroll
    for (int off = 16; off; off >>= 1) acc += __shfl_down_sync(0xffffffffu, acc, off);
    if (lane == 0) g_e2[warp] = acc;
}

// ---------------- B chunk issue: contiguous 32 KB permuted chunk ------------
__device__ __forceinline__ void issueB(uint32_t sb, int chunk, int tid) {
    uint32_t bbuf = sb + ((chunk & 1) ? SMB1 : SMB0);
    const char* src = (const char*)g_Cb + (size_t)chunk * 32768;
#pragma unroll
    for (int t = 0; t < 8; t++) {
        int q = tid + t * NTHR;              // 2048 x 16B
        cp16(bbuf + q * 16, src + (size_t)q * 16);
    }
    asm volatile("cp.async.commit_group;" ::: "memory");
}

// ---------------- bf16 mma distance kernel + candidate capture --------------
__global__ __launch_bounds__(NTHR, 2)
void dist_mma_kernel(const float* __restrict__ Z) {
    extern __shared__ char sm[];
    const uint32_t sb = smem_u32(sm);
    const int tid  = threadIdx.x;
    const int wid  = tid >> 5;
    const int lane = tid & 31;
    const int g    = lane >> 2;
    const int tq   = lane & 3;
    const int wr   = wid >> 2;           // 0..1 : 32-row slab
    const int wc   = wid & 3;            // 0..3 : 64-code slab
    const int rowBase = blockIdx.x * BM;
    float* qbuf = (float*)(sm + SMQB);   // [64][4]

    issueB(sb, 0, tid);                  // async B0 overlaps A staging

    // ---- stage A (64 x 256) fp32 -> bf16 pairs, fragment-permuted (proven) ----
#pragma unroll
    for (int l = 0; l < 16; l++) {
        int i4 = tid + l * NTHR;         // 4096 float4
        int r  = i4 >> 6;
        int c4 = i4 & 63;
        float4 v = *(const float4*)(Z + (size_t)(rowBase + r) * DIM + c4 * 4);
        uint32_t p0 = packbf(v.x, v.y);
        uint32_t p1 = packbf(v.z, v.w);
        int r16 = r & 15, mtG = r >> 4;  // mtG 0..3
        int rowPart = ((r16 & 7) * 4) * 16 + ((r16 >> 3) & 1) * 4;
#pragma unroll
        for (int pi = 0; pi < 2; pi++) {
            int c = 2 * c4 + pi;
            int kt = c >> 3, c8 = c & 7;
            int off = (mtG * 16 + kt) * ATILE + rowPart + (c8 & 3) * 16 + ((c8 >> 2) * 2) * 4;
            *(uint32_t*)(sm + off) = pi ? p1 : p0;
        }
    }

    float wmRun[2][2];
    wmRun[0][0] = wmRun[0][1] = wmRun[1][0] = wmRun[1][1] = __int_as_float(0x7f800000);

    for (int ct = 0; ct < NCT; ct++) {
        float acc[2][8][4];
#pragma unroll
        for (int a = 0; a < 2; a++)
#pragma unroll
            for (int b = 0; b < 8; b++)
#pragma unroll
                for (int e = 0; e < 4; e++) acc[a][b][e] = 0.f;

        for (int kc = 0; kc < NKC; kc++) {
            const int chunk = ct * NKC + kc;
            asm volatile("cp.async.wait_group 0;" ::: "memory");
            __syncthreads();
            if (chunk + 1 < NCHUNK) issueB(sb, chunk + 1, tid);

            const uint32_t bo = (uint32_t)((chunk & 1) ? SMB1 : SMB0);
#pragma unroll
            for (int ks = 0; ks < 4; ks++) {          // four k16 steps per chunk
                uint4 afr[2];
#pragma unroll
                for (int mt = 0; mt < 2; mt++)
                    afr[mt] = *(const uint4*)(sm + ((wr * 2 + mt) * 16 + kc * 4 + ks) * ATILE + lane * 16);
#pragma unroll
                for (int pp = 0; pp < 4; pp++) {      // 4 ntpairs = 8 nt per warp
                    uint4 bfr = *(const uint4*)(sm + bo + (((ks * 16 + wc * 4 + pp) * 32) + lane) * 16);
#pragma unroll
                    for (int mt = 0; mt < 2; mt++) {
                        mma_bf16(acc[mt][pp * 2],     afr[mt], bfr.x, bfr.y);
                        mma_bf16(acc[mt][pp * 2 + 1], afr[mt], bfr.z, bfr.w);
                    }
                }
            }
        }

        // ---- epilogue: dist = e2 - 2*ze, running rowmin, candidate append ----
        const int ctbase = ct * BN;
        float e2v[8][2];
#pragma unroll
        for (int nt = 0; nt < 8; nt++) {
            int c = ctbase + wc * 64 + nt * 8 + 2 * tq;
            e2v[nt][0] = __ldg(&g_e2[c]);
            e2v[nt][1] = __ldg(&g_e2[c + 1]);
        }
        float tmin[2][2];                 // tile-local row min (this warp's 64 codes)
#pragma unroll
        for (int mt = 0; mt < 2; mt++)
#pragma unroll
            for (int h = 0; h < 2; h++) {
                float m = __int_as_float(0x7f800000);
#pragma unroll
                for (int nt = 0; nt < 8; nt++)
#pragma unroll
                    for (int c01 = 0; c01 < 2; c01++) {
                        int ai = h * 2 + c01;
                        float d = fmaf(-2.f, acc[mt][nt][ai], e2v[nt][c01]);
                        acc[mt][nt][ai] = d;
                        m = fminf(m, d);
                    }
                m = fminf(m, __shfl_xor_sync(0xffffffffu, m, 1));
                m = fminf(m, __shfl_xor_sync(0xffffffffu, m, 2));
                tmin[mt][h] = m;          // min over warp's 64 codes for this row
                wmRun[mt][h] = fminf(wmRun[mt][h], m);
                if (tq == 0)
                    qbuf[(wr * 32 + mt * 16 + g + h * 8) * 4 + wc] = wmRun[mt][h];
            }
        __syncthreads();
#pragma unroll
        for (int mt = 0; mt < 2; mt++)
#pragma unroll
            for (int h = 0; h < 2; h++) {
                int r = wr * 32 + mt * 16 + g + h * 8;   // covers 0..63
                float th = fminf(fminf(qbuf[r * 4 + 0], qbuf[r * 4 + 1]),
                                 fminf(qbuf[r * 4 + 2], qbuf[r * 4 + 3])) + MARGIN;
                // EARLY SKIP: if this warp's tile min for the row can't beat th,
                // no element can (exact: tmin >= th  =>  all d >= th).
                if (!(tmin[mt][h] < th)) continue;
                int grow = rowBase + r;
#pragma unroll
                for (int nt = 0; nt < 8; nt++)
#pragma unroll
                    for (int c01 = 0; c01 < 2; c01++) {
                        float d = acc[mt][nt][h * 2 + c01];
                        if (d < th) {
                            int code = ctbase + wc * 64 + nt * 8 + 2 * tq + c01;
                            int pos = atomicAdd(&g_candCnt[grow], 1);
                            if (pos < CAP) g_candIdx[grow * CAP + pos] = code;
                        }
                    }
            }
        // next ct's qbuf writes are separated by its first-chunk barrier
    }
}

// ---------------- exact refine + fused gather/output/loss -------------------
__device__ __forceinline__ float exact_dist(const float4* __restrict__ zr, int code,
                                            const float* __restrict__ C, float z2) {
    const float4* cr = (const float4*)(C + (size_t)code * DIM);
    float acc = 0.f;
#pragma unroll 4
    for (int d4 = 0; d4 < 64; d4++) {
        float4 a = zr[d4], b = cr[d4];
        acc = fmaf(a.x, b.x, acc); acc = fmaf(a.y, b.y, acc);
        acc = fmaf(a.z, b.z, acc); acc = fmaf(a.w, b.w, acc);
    }
    float t = z2 + g_e2[code];
    return fmaf(-2.f, acc, t);
}

__global__ __launch_bounds__(256, 6)
void refine_gather_kernel(const float* __restrict__ Z, const float* __restrict__ C,
                          float* __restrict__ outZ, float* __restrict__ outIdx) {
    int gt = blockIdx.x * blockDim.x + threadIdx.x;
    int row = gt >> 3, slot = gt & 7;
    if (row >= BATCH) return;
    int cnt = g_candCnt[row];
    const float4* zr = (const float4*)(Z + (size_t)row * DIM);
    float z2 = g_z2[row];
    float bd = __int_as_float(0x7f800000);
    int bi = 0x7fffffff;
    if (cnt > 0 && cnt <= CAP) {
        for (int s = slot; s < cnt; s += 8) {
            int code = g_candIdx[row * CAP + s];
            float dist = exact_dist(zr, code, C, z2);
            if (dist < bd || (dist == bd && code < bi)) { bd = dist; bi = code; }
        }
    } else {  // overflow OR empty (defensive): exact full scan
        for (int code = slot; code < NCODES; code += 8) {
            float dist = exact_dist(zr, code, C, z2);
            if (dist < bd || (dist == bd && code < bi)) { bd = dist; bi = code; }
        }
    }
#pragma unroll
    for (int off = 4; off; off >>= 1) {          // xor butterfly: all 8 lanes get result
        float od = __shfl_xor_sync(0xffffffffu, bd, off);
        int oi = __shfl_xor_sync(0xffffffffu, bi, off);
        if (od < bd || (od == bd && oi < bi)) { bd = od; bi = oi; }
    }
    const float4* er = (const float4*)(C + (size_t)bi * DIM);
    float4* orow = (float4*)(outZ + (size_t)row * DIM);
    double s = 0.0;
#pragma unroll
    for (int j = 0; j < 8; j++) {
        int i = slot * 8 + j;
        float4 z = zr[i], e = er[i];
        float dx = e.x - z.x, dy = e.y - z.y, dz = e.z - z.z, dw = e.w - z.w;
        float4 o;
        o.x = z.x + dx; o.y = z.y + dy; o.z = z.z + dz; o.w = z.w + dw;
        orow[i] = o;
        s += (double)(dx * dx) + (double)(dy * dy) + (double)(dz * dz) + (double)(dw * dw);
    }
#pragma unroll
    for (int off = 4; off; off >>= 1) s += __shfl_xor_sync(0xffffffffu, s, off);
    if (slot == 0) { g_part[row] = s; outIdx[row] = (float)bi; }
}

__global__ void finalize_kernel(float* __restrict__ outS) {
    __shared__ double red[256];
    int t = threadIdx.x;
    double s = 0.0;
    for (int i = t; i < BATCH; i += 256) s += g_part[i];
    red[t] = s;
    __syncthreads();
#pragma unroll
    for (int off = 128; off; off >>= 1) {
        if (t < off) red[t] += red[t + off];
        __syncthreads();
    }
    if (t == 0) {
        float cb = (float)(red[0] / (double)((size_t)BATCH * DIM));
        float commit = cb;
        float vq = cb + 0.25f * commit;
        outS[0] = vq; outS[1] = cb; outS[2] = commit;
    }
}

// ---------------------------------------------------------------------------
extern "C" void kernel_launch(void* const* d_in, const int* in_sizes, int n_in,
                              void* d_out, int out_size) {
    (void)in_sizes; (void)n_in; (void)out_size;
    const float* Z = (const float*)d_in[0];
    const float* C = (const float*)d_in[1];
    float* out    = (float*)d_out;
    float* outZ   = out;
    float* outIdx = out + (size_t)BATCH * DIM;
    float* outS   = outIdx + BATCH;

    static bool attrSet = false;
    if (!attrSet) {
        cudaFuncSetAttribute(dist_mma_kernel,
                             cudaFuncAttributeMaxDynamicSharedMemorySize, SM_TOT);
        attrSet = true;
    }

    cvtC_kernel<<<(NCODES * DIM / 4) / 256, 256>>>(C);
    rowsq_z_kernel<<<(BATCH * 32) / 256, 256>>>(Z);
    rowsq_e_kernel<<<(NCODES * 32) / 256, 256>>>(C);
    dist_mma_kernel<<<BATCH / BM, NTHR, SM_TOT>>>(Z);
    refine_gather_kernel<<<(BATCH * 8) / 256, 256>>>(Z, C, outZ, outIdx);
    finalize_kernel<<<1, 256>>>(outS);
}